// round 15
// baseline (speedup 1.0000x reference)
#include <cuda_runtime.h>
#include <cuda_fp16.h>
#include <cstdint>
#include <math.h>

#define BB 2
#define NN 2048
#define CC 1024
#define HH 16
#define DD 64
#define E3 3072
#define MM (BB*NN)   // 4096
#define BH (BB*HH)   // 32

// Q scale: 1/sqrt(64) * log2(e)
#define QSCALE 0.1803368801111204f

// ---------------- scratch (no allocations allowed) ----------------
__device__ __half g_qh[BH * NN * DD];
__device__ __half g_kh[BH * NN * DD];
__device__ __half g_vh[BH * NN * DD];
__device__ __half g_aoh[MM * CC];
__device__ __half g_wqh[E3 * CC];
__device__ __half g_woh[CC * CC];

__device__ __forceinline__ float ex2f(float x) {
    float r;
    asm("ex2.approx.f32 %0, %1;" : "=f"(r) : "f"(x));
    return r;
}
__device__ __forceinline__ uint32_t smem_u32(const void* p) {
    uint32_t a;
    asm("{ .reg .u64 t; cvta.to.shared.u64 t, %1; cvt.u32.u64 %0, t; }" : "=r"(a) : "l"(p));
    return a;
}
__device__ __forceinline__ void mma16816(float* c, const uint32_t* a, const uint32_t* b) {
    asm volatile("mma.sync.aligned.m16n8k16.row.col.f32.f16.f16.f32 "
        "{%0,%1,%2,%3}, {%4,%5,%6,%7}, {%8,%9}, {%0,%1,%2,%3};"
        : "+f"(c[0]), "+f"(c[1]), "+f"(c[2]), "+f"(c[3])
        : "r"(a[0]), "r"(a[1]), "r"(a[2]), "r"(a[3]), "r"(b[0]), "r"(b[1]));
}
__device__ __forceinline__ void ldsm_x4(uint32_t* r, uint32_t addr) {
    asm volatile("ldmatrix.sync.aligned.m8n8.x4.shared.b16 {%0,%1,%2,%3}, [%4];"
        : "=r"(r[0]), "=r"(r[1]), "=r"(r[2]), "=r"(r[3]) : "r"(addr));
}
__device__ __forceinline__ void ldsm_x4t(uint32_t* r, uint32_t addr) {
    asm volatile("ldmatrix.sync.aligned.m8n8.x4.trans.shared.b16 {%0,%1,%2,%3}, [%4];"
        : "=r"(r[0]), "=r"(r[1]), "=r"(r[2]), "=r"(r[3]) : "r"(addr));
}
// pack two fp32 into f16x2 with one cvt
__device__ __forceinline__ uint32_t packf16x2(float lo, float hi) {
    uint32_t d;
    asm("cvt.rn.f16x2.f32 %0, %1, %2;" : "=r"(d) : "f"(hi), "f"(lo));
    return d;
}
__device__ __forceinline__ void cvt_hi(float4 v, uint2& h) {
    h.x = packf16x2(v.x, v.y);
    h.y = packf16x2(v.z, v.w);
}
__device__ __forceinline__ void cp16(uint32_t saddr, const void* gaddr) {
    asm volatile("cp.async.cg.shared.global [%0], [%1], 16;" :: "r"(saddr), "l"(gaddr));
}
#define CP_COMMIT() asm volatile("cp.async.commit_group;" ::: "memory")
#define CP_WAIT0()  asm volatile("cp.async.wait_group 0;" ::: "memory")
#define CP_WAIT1()  asm volatile("cp.async.wait_group 1;" ::: "memory")

// ---------------- weight conversion: fp32 -> fp16 ----------------
__global__ __launch_bounds__(256) void whalf_kernel(const float* __restrict__ src,
                                                    int which, int n4)
{
    __half* hi = (which == 0) ? g_wqh : g_woh;
    int i = blockIdx.x * blockDim.x + threadIdx.x;
    if (i >= n4) return;
    float4 a = ((const float4*)src)[i];
    uint2 h;
    cvt_hi(a, h);
    *(uint2*)(hi + (size_t)i * 4) = h;
}

// ---------------- mma.sync 1-term GEMM (both projections) ----------------
// MODE 0 (qkv): A = x fp32 -> fp16 inline (STS). Epilogue: Q/K/V fp16.
// MODE 1 (proj): A = g_aoh fp16 via cp.async. Out fp32 + bias.
// smem stage: A[128][40]h @0, B[128][40]h @10240 B; stage stride 20480 B.
#define GSMEM 40960
template<int MODE>
__global__ __launch_bounds__(512) void tc_gemm(const float* __restrict__ Ain,
                                               const float* __restrict__ bias,
                                               float* __restrict__ outp)
{
    extern __shared__ __half sm[];
    const int tid  = threadIdx.x;
    const int lane = tid & 31;
    const int wid  = tid >> 5;
    const int wm   = wid >> 2;
    const int wn   = wid & 3;
    const int m0 = blockIdx.y * 128;
    const int n0 = blockIdx.x * 128;

    const __half* pBh = (MODE == 0) ? g_wqh : g_woh;

    const uint32_t sbase = smem_u32(sm);
    const uint32_t a_row  = wm * 32 + (lane & 15);
    const uint32_t a_kg   = (lane >> 4) << 3;
    const uint32_t b_kg   = ((lane >> 3) & 1) << 3;
    const uint32_t b_row4 = wn * 32 + (lane & 7) + (((lane >> 4) & 1) << 3);

    const int brow = tid >> 2;
    const int bkgc = (tid & 3) * 8;
    const __half* gBh = pBh + (size_t)(n0 + brow) * CC + bkgc;
    const __half* gAh = g_aoh + (size_t)(m0 + brow) * CC + bkgc;   // MODE 1
    const uint32_t coff = (uint32_t)(brow * 40 + bkgc) * 2;

    float acc[2][4][4];
#pragma unroll
    for (int i = 0; i < 2; i++)
#pragma unroll
        for (int j = 0; j < 4; j++)
#pragma unroll
            for (int c = 0; c < 4; c++) acc[i][j][c] = 0.0f;

    float4 ra[2];
    if (MODE == 0) {
#pragma unroll
        for (int i = 0; i < 2; i++) {
            int slot = tid + i * 512;
            int row = slot >> 3, c4 = (slot & 7) * 4;
            ra[i] = *(const float4*)&Ain[(size_t)(m0 + row) * CC + c4];
        }
    }

    auto store_A = [&](int st) {
#pragma unroll
        for (int i = 0; i < 2; i++) {
            int slot = tid + i * 512;
            int row = slot >> 3, c = (slot & 7) * 4;
            uint2 h;
            cvt_hi(ra[i], h);
            *(uint2*)&sm[st * 10240 + row * 40 + c] = h;
        }
    };
    auto issue_tiles = [&](int st, int k0) {
        uint32_t base = sbase + st * 20480;
        cp16(base + 10240 + coff, gBh + k0);
        if (MODE == 1) cp16(base + coff, gAh + k0);
    };

    issue_tiles(0, 0);
    CP_COMMIT();
    if (MODE == 0) store_A(0);
    CP_WAIT0();
    __syncthreads();

    for (int k0 = 0; k0 < CC; k0 += 32) {
        const int st   = (k0 >> 5) & 1;
        const bool nxt = (k0 + 32 < CC);

        if (nxt) {
            issue_tiles(st ^ 1, k0 + 32);
            CP_COMMIT();
            if (MODE == 0) {
#pragma unroll
                for (int i = 0; i < 2; i++) {
                    int slot = tid + i * 512;
                    int row = slot >> 3, c4 = (slot & 7) * 4;
                    ra[i] = *(const float4*)&Ain[(size_t)(m0 + row) * CC + k0 + 32 + c4];
                }
            }
        }

        const uint32_t base = sbase + st * 20480;
#pragma unroll
        for (int ks = 0; ks < 2; ks++) {
            const uint32_t kcol = ks * 16;
            uint32_t ah[2][4];
#pragma unroll
            for (int mt = 0; mt < 2; mt++) {
                uint32_t off = ((a_row + mt * 16) * 40 + kcol + a_kg) * 2;
                ldsm_x4(ah[mt], base + off);
            }
#pragma unroll
            for (int ntp = 0; ntp < 2; ntp++) {
                uint32_t boff = ((b_row4 + ntp * 16) * 40 + kcol + b_kg) * 2;
                uint32_t bb[4];
                ldsm_x4(bb, base + 10240 + boff);
#pragma unroll
                for (int mt = 0; mt < 2; mt++) {
                    mma16816(acc[mt][ntp * 2 + 0], ah[mt], bb);
                    mma16816(acc[mt][ntp * 2 + 1], ah[mt], bb + 2);
                }
            }
            if (MODE == 0 && ks == 0 && nxt) store_A(st ^ 1);
        }

        if (nxt) CP_WAIT0();
        __syncthreads();
    }

    // Epilogue
#pragma unroll
    for (int mt = 0; mt < 2; mt++) {
#pragma unroll
        for (int nt = 0; nt < 4; nt++) {
            const float* c = acc[mt][nt];
            const int col = n0 + wn * 32 + nt * 8 + (lane & 3) * 2;
#pragma unroll
            for (int hr = 0; hr < 2; hr++) {
                const int row = m0 + wm * 32 + mt * 16 + (lane >> 2) + hr * 8;
                float vx = c[hr * 2 + 0], vy = c[hr * 2 + 1];
                if (MODE == 0) {
                    const int part = col >> 10, rr = col & 1023;
                    const int h = rr >> 6, d = rr & 63;
                    const int b = row >> 11, n = row & 2047;
                    const size_t addr = ((size_t)(b * HH + h) * NN + n) * DD + d;
                    if (part == 0) { vx *= QSCALE; vy *= QSCALE; }
                    __half* dst = (part == 0) ? g_qh : (part == 1) ? g_kh : g_vh;
                    *(uint32_t*)&dst[addr] = packf16x2(vx, vy);
                } else {
                    vx += bias[col];
                    vy += bias[col + 1];
                    *(float2*)&outp[(size_t)row * CC + col] = make_float2(vx, vy);
                }
            }
        }
    }
}

// ---------------- MMA flash attention: fp16, x4 ldmatrix, f16x2 packing ------
// Smem: 2 stages x (Kh|Vh)[64][72] = 36864 B. Qh staging overlays stage 0.
#define ATT_SMEM 36864
__global__ __launch_bounds__(256, 2) void attn_mma_kernel()
{
    extern __shared__ __half smh[];
    const int bh   = blockIdx.y;
    const int q0   = blockIdx.x * 128;
    const int tid  = threadIdx.x;
    const int lane = tid & 31;
    const int warp = tid >> 5;

    const uint32_t sbase = smem_u32(smh);
    const size_t hb = (size_t)bh * NN * DD;
    const __half* kvsrc[2] = { g_kh + hb, g_vh + hb };

    // ---- prologue: Qh (stage-0 region) + KV tile 0 (stage 1) ----
#pragma unroll
    for (int i = 0; i < 4; i++) {
        const int s = tid + i * 256;
        const int row = s >> 3, c = (s & 7) * 8;
        cp16(sbase + (row * 72 + c) * 2, g_qh + hb + (size_t)(q0 + row) * DD + c);
    }
    CP_COMMIT();
#pragma unroll
    for (int i = 0; i < 4; i++) {
        const int mat = i >> 1;
        const int s = tid + (i & 1) * 256;
        const int row = s >> 3, c = (s & 7) * 8;
        cp16(sbase + 18432 + mat * 9216 + (row * 72 + c) * 2,
             kvsrc[mat] + (size_t)row * DD + c);
    }
    CP_COMMIT();
    CP_WAIT1();
    __syncthreads();

    // ---- Q fragments ----
    uint32_t qh[4][4];
    {
        const uint32_t arow = warp * 16 + (lane & 15);
        const uint32_t akg  = ((lane >> 4) & 1) * 8;
#pragma unroll
        for (int ks = 0; ks < 4; ks++)
            ldsm_x4(qh[ks], sbase + (arow * 72 + ks * 16 + akg) * 2);
    }
    __syncthreads();

    float O[8][4];
#pragma unroll
    for (int n = 0; n < 8; n++)
#pragma unroll
        for (int c = 0; c < 4; c++) O[n][c] = 0.0f;
    float m0r = -1e30f, m1r = -1e30f;
    float l0 = 0.0f, l1 = 0.0f;

    const uint32_t b_kg   = ((lane >> 3) & 1) * 8;
    const uint32_t b_row4 = (lane & 7) + (((lane >> 4) & 1) << 3);

    for (int t = 0; t < 32; t++) {
        const uint32_t base = sbase + ((t & 1) ? 0u : 18432u);

        if (t + 1 < 32) {
            const uint32_t nbase = sbase + ((t & 1) ? 18432u : 0u);
            const int j0 = (t + 1) * 64;
#pragma unroll
            for (int i = 0; i < 4; i++) {
                const int mat = i >> 1;
                const int s = tid + (i & 1) * 256;
                const int row = s >> 3, c = (s & 7) * 8;
                cp16(nbase + mat * 9216 + (row * 72 + c) * 2,
                     kvsrc[mat] + (size_t)(j0 + row) * DD + c);
            }
            CP_COMMIT();
            CP_WAIT1();
        } else {
            CP_WAIT0();
        }
        __syncthreads();

        // ---- scores: QhKh (log2 domain), x4 K fragments ----
        float s[8][4];
#pragma unroll
        for (int n = 0; n < 8; n++)
#pragma unroll
            for (int c = 0; c < 4; c++) s[n][c] = 0.0f;

#pragma unroll
        for (int ks = 0; ks < 4; ks++) {
#pragma unroll
            for (int ntp = 0; ntp < 4; ntp++) {
                uint32_t boff = ((b_row4 + ntp * 16) * 72 + ks * 16 + b_kg) * 2;
                uint32_t kb[4];
                ldsm_x4(kb, base + boff);
                mma16816(s[ntp * 2 + 0], qh[ks], kb);
                mma16816(s[ntp * 2 + 1], qh[ks], kb + 2);
            }
        }

        // ---- online softmax (exp2) ----
        float mloc0 = -1e30f, mloc1 = -1e30f;
#pragma unroll
        for (int nt = 0; nt < 8; nt++) {
            mloc0 = fmaxf(mloc0, fmaxf(s[nt][0], s[nt][1]));
            mloc1 = fmaxf(mloc1, fmaxf(s[nt][2], s[nt][3]));
        }
        mloc0 = fmaxf(mloc0, __shfl_xor_sync(0xffffffffu, mloc0, 1));
        mloc0 = fmaxf(mloc0, __shfl_xor_sync(0xffffffffu, mloc0, 2));
        mloc1 = fmaxf(mloc1, __shfl_xor_sync(0xffffffffu, mloc1, 1));
        mloc1 = fmaxf(mloc1, __shfl_xor_sync(0xffffffffu, mloc1, 2));

        float mn0 = fmaxf(m0r, mloc0), mn1 = fmaxf(m1r, mloc1);
        float cr0 = ex2f(m0r - mn0), cr1 = ex2f(m1r - mn1);
        m0r = mn0; m1r = mn1;
        l0 *= cr0; l1 *= cr1;
#pragma unroll
        for (int n = 0; n < 8; n++) {
            O[n][0] *= cr0; O[n][1] *= cr0;
            O[n][2] *= cr1; O[n][3] *= cr1;
        }

        float ls0 = 0.0f, ls1 = 0.0f;
        uint32_t aPh[4][4];
#pragma unroll
        for (int nt = 0; nt < 8; nt++) {
            float p0 = ex2f(s[nt][0] - m0r);
            float p1 = ex2f(s[nt][1] - m0r);
            float p2 = ex2f(s[nt][2] - m1r);
            float p3 = ex2f(s[nt][3] - m1r);
            ls0 += p0 + p1; ls1 += p2 + p3;
            const int kt = nt >> 1, hi2 = (nt & 1) * 2;
            aPh[kt][hi2 + 0] = packf16x2(p0, p1);
            aPh[kt][hi2 + 1] = packf16x2(p2, p3);
        }
        ls0 += __shfl_xor_sync(0xffffffffu, ls0, 1);
        ls0 += __shfl_xor_sync(0xffffffffu, ls0, 2);
        ls1 += __shfl_xor_sync(0xffffffffu, ls1, 1);
        ls1 += __shfl_xor_sync(0xffffffffu, ls1, 2);
        l0 += ls0; l1 += ls1;

        // ---- O += PhVh, x4 trans V fragments (kt pairs) ----
#pragma unroll
        for (int ktp = 0; ktp < 2; ktp++) {
#pragma unroll
            for (int nd = 0; nd < 8; nd++) {
                uint32_t voff = ((ktp * 32 + lane) * 72 + nd * 8) * 2;
                uint32_t vb[4];
                ldsm_x4t(vb, base + 9216 + voff);
                mma16816(O[nd], aPh[ktp * 2 + 0], vb);
                mma16816(O[nd], aPh[ktp * 2 + 1], vb + 2);
            }
        }
        __syncthreads();
    }

    // ---- epilogue: fp16 attention output ----
    const float inv0 = 1.0f / l0, inv1 = 1.0f / l1;
    const int b = bh >> 4, h = bh & 15;
    const int row0 = q0 + warp * 16 + (lane >> 2);
    const int row1 = row0 + 8;
#pragma unroll
    for (int nd = 0; nd < 8; nd++) {
        const int d = nd * 8 + (lane & 3) * 2;
        const size_t a0 = ((size_t)(b * NN + row0)) * CC + h * DD + d;
        const size_t a1 = ((size_t)(b * NN + row1)) * CC + h * DD + d;
        *(uint32_t*)&g_aoh[a0] = packf16x2(O[nd][0] * inv0, O[nd][1] * inv0);
        *(uint32_t*)&g_aoh[a1] = packf16x2(O[nd][2] * inv1, O[nd][3] * inv1);
    }
}

// ---------------------------------------------------------------------------
extern "C" void kernel_launch(void* const* d_in, const int* in_sizes, int n_in,
                              void* d_out, int out_size)
{
    const float* x     = (const float*)d_in[0];
    const float* W_qkv = (const float*)d_in[1];
    const float* W_out = (const float*)d_in[2];
    const float* b_out = (const float*)d_in[3];
    float* out = (float*)d_out;
    (void)in_sizes; (void)n_in; (void)out_size;

    cudaFuncSetAttribute(tc_gemm<0>, cudaFuncAttributeMaxDynamicSharedMemorySize, GSMEM);
    cudaFuncSetAttribute(tc_gemm<1>, cudaFuncAttributeMaxDynamicSharedMemorySize, GSMEM);
    cudaFuncSetAttribute(attn_mma_kernel, cudaFuncAttributeMaxDynamicSharedMemorySize, ATT_SMEM);

    whalf_kernel<<<(E3 * CC / 4 + 255) / 256, 256>>>(W_qkv, 0, E3 * CC / 4);
    whalf_kernel<<<(CC * CC / 4 + 255) / 256, 256>>>(W_out, 1, CC * CC / 4);

    {
        dim3 grid(E3 / 128, MM / 128);   // (24, 32)
        tc_gemm<0><<<grid, 512, GSMEM>>>(x, nullptr, nullptr);
    }
    {
        dim3 grid(NN / 128, BH);         // (16, 32)
        attn_mma_kernel<<<grid, 256, ATT_SMEM>>>();
    }
    {
        dim3 grid(CC / 128, MM / 128);   // (8, 32)
        tc_gemm<1><<<grid, 512, GSMEM>>>(nullptr, b_out, out);
    }
}

// round 16
// speedup vs baseline: 1.0979x; 1.0979x over previous
#include <cuda_runtime.h>
#include <cuda_fp16.h>
#include <cstdint>
#include <math.h>

#define BB 2
#define NN 2048
#define CC 1024
#define HH 16
#define DD 64
#define E3 3072
#define MM (BB*NN)   // 4096
#define BH (BB*HH)   // 32

// Q scale: 1/sqrt(64) * log2(e)
#define QSCALE 0.1803368801111204f

// ---------------- scratch (no allocations allowed) ----------------
__device__ __half g_qh[BH * NN * DD];
__device__ __half g_kh[BH * NN * DD];
__device__ __half g_vh[BH * NN * DD];
__device__ __half g_aoh[MM * CC];
__device__ __half g_wqh[E3 * CC];
__device__ __half g_woh[CC * CC];

__device__ __forceinline__ float ex2f(float x) {
    float r;
    asm("ex2.approx.f32 %0, %1;" : "=f"(r) : "f"(x));
    return r;
}
__device__ __forceinline__ uint32_t smem_u32(const void* p) {
    uint32_t a;
    asm("{ .reg .u64 t; cvta.to.shared.u64 t, %1; cvt.u32.u64 %0, t; }" : "=r"(a) : "l"(p));
    return a;
}
__device__ __forceinline__ void mma16816(float* c, const uint32_t* a, const uint32_t* b) {
    asm volatile("mma.sync.aligned.m16n8k16.row.col.f32.f16.f16.f32 "
        "{%0,%1,%2,%3}, {%4,%5,%6,%7}, {%8,%9}, {%0,%1,%2,%3};"
        : "+f"(c[0]), "+f"(c[1]), "+f"(c[2]), "+f"(c[3])
        : "r"(a[0]), "r"(a[1]), "r"(a[2]), "r"(a[3]), "r"(b[0]), "r"(b[1]));
}
__device__ __forceinline__ void ldsm_x4(uint32_t* r, uint32_t addr) {
    asm volatile("ldmatrix.sync.aligned.m8n8.x4.shared.b16 {%0,%1,%2,%3}, [%4];"
        : "=r"(r[0]), "=r"(r[1]), "=r"(r[2]), "=r"(r[3]) : "r"(addr));
}
__device__ __forceinline__ void ldsm_x4t(uint32_t* r, uint32_t addr) {
    asm volatile("ldmatrix.sync.aligned.m8n8.x4.trans.shared.b16 {%0,%1,%2,%3}, [%4];"
        : "=r"(r[0]), "=r"(r[1]), "=r"(r[2]), "=r"(r[3]) : "r"(addr));
}
__device__ __forceinline__ uint32_t packf16x2(float lo, float hi) {
    uint32_t d;
    asm("cvt.rn.f16x2.f32 %0, %1, %2;" : "=r"(d) : "f"(hi), "f"(lo));
    return d;
}
__device__ __forceinline__ void cvt_hi(float4 v, uint2& h) {
    h.x = packf16x2(v.x, v.y);
    h.y = packf16x2(v.z, v.w);
}
__device__ __forceinline__ void cp16(uint32_t saddr, const void* gaddr) {
    asm volatile("cp.async.cg.shared.global [%0], [%1], 16;" :: "r"(saddr), "l"(gaddr));
}
#define CP_COMMIT() asm volatile("cp.async.commit_group;" ::: "memory")
#define CP_WAIT0()  asm volatile("cp.async.wait_group 0;" ::: "memory")
#define CP_WAIT1()  asm volatile("cp.async.wait_group 1;" ::: "memory")

// ---------------- weight conversion: both weights, one launch ----------------
#define NQ4 (E3 * CC / 4)
#define NO4 (CC * CC / 4)
__global__ __launch_bounds__(256) void whalf_kernel(const float* __restrict__ wq,
                                                    const float* __restrict__ wo)
{
    int i = blockIdx.x * blockDim.x + threadIdx.x;
    if (i < NQ4) {
        float4 a = ((const float4*)wq)[i];
        uint2 h; cvt_hi(a, h);
        *(uint2*)(g_wqh + (size_t)i * 4) = h;
    } else if (i < NQ4 + NO4) {
        int j = i - NQ4;
        float4 a = ((const float4*)wo)[j];
        uint2 h; cvt_hi(a, h);
        *(uint2*)(g_woh + (size_t)j * 4) = h;
    }
}

// ---------------- mma.sync 1-term GEMM, BK=64 ----------------
// MODE 0 (qkv): A = x fp32 -> fp16 inline. Epilogue Q/K/V fp16 (Q pre-scaled).
// MODE 1 (proj): A = g_aoh fp16 via cp.async. Out fp32 + bias.
// Stage (bytes): A[128][72]h @0 (18432), B[128][72]h @18432; stage stride 36864.
#define GSMEM 73728
template<int MODE>
__global__ __launch_bounds__(512) void tc_gemm(const float* __restrict__ Ain,
                                               const float* __restrict__ bias,
                                               float* __restrict__ outp)
{
    extern __shared__ __half sm[];
    const int tid  = threadIdx.x;
    const int lane = tid & 31;
    const int wid  = tid >> 5;
    const int wm   = wid >> 2;
    const int wn   = wid & 3;
    const int m0 = blockIdx.y * 128;
    const int n0 = blockIdx.x * 128;

    const __half* pBh = (MODE == 0) ? g_wqh : g_woh;

    const uint32_t sbase = smem_u32(sm);
    const uint32_t a_row  = wm * 32 + (lane & 15);
    const uint32_t a_kg   = (lane >> 4) << 3;
    const uint32_t b_kg   = ((lane >> 3) & 1) << 3;
    const uint32_t b_row4 = wn * 32 + (lane & 7) + (((lane >> 4) & 1) << 3);

    // B/A-fp16 cp.async slots: 1024 16B-chunks per matrix per 64-chunk; 2/thread
    const int crow = ((tid << 1) | 0) >> 4;   // rows for slot pair
    const __half* gBh = pBh + (size_t)n0 * CC;
    const __half* gAh = g_aoh + (size_t)m0 * CC;   // MODE 1

    float acc[2][4][4];
#pragma unroll
    for (int i = 0; i < 2; i++)
#pragma unroll
        for (int j = 0; j < 4; j++)
#pragma unroll
            for (int c = 0; c < 4; c++) acc[i][j][c] = 0.0f;

    // A fp32 loads (MODE 0): 2048 float4 per chunk, 4/thread
    float4 ra[4];
    auto load_A = [&](int k0) {
#pragma unroll
        for (int i = 0; i < 4; i++) {
            int slot = tid + i * 512;
            int row = slot >> 4, c4 = (slot & 15) * 4;
            ra[i] = *(const float4*)&Ain[(size_t)(m0 + row) * CC + k0 + c4];
        }
    };
    auto store_A = [&](int st) {
#pragma unroll
        for (int i = 0; i < 4; i++) {
            int slot = tid + i * 512;
            int row = slot >> 4, c = (slot & 15) * 4;
            uint2 h;
            cvt_hi(ra[i], h);
            *(uint2*)&sm[st * 18432 + row * 72 + c] = h;
        }
    };
    auto issue_tiles = [&](int st, int k0) {
        uint32_t base = sbase + st * 36864;
#pragma unroll
        for (int i = 0; i < 2; i++) {
            int slot = tid + i * 512;
            int row = slot >> 3, c = (slot & 7) * 8;
            cp16(base + 18432 + (row * 72 + c) * 2, gBh + (size_t)row * CC + k0 + c);
            if (MODE == 1)
                cp16(base + (row * 72 + c) * 2, gAh + (size_t)row * CC + k0 + c);
        }
    };

    issue_tiles(0, 0);
    CP_COMMIT();
    if (MODE == 0) { load_A(0); store_A(0); }
    CP_WAIT0();
    __syncthreads();

    for (int k0 = 0; k0 < CC; k0 += 64) {
        const int st   = (k0 >> 6) & 1;
        const bool nxt = (k0 + 64 < CC);

        if (nxt) {
            issue_tiles(st ^ 1, k0 + 64);
            CP_COMMIT();
            if (MODE == 0) load_A(k0 + 64);
        }

        const uint32_t base = sbase + st * 36864;
#pragma unroll
        for (int ks = 0; ks < 4; ks++) {
            const uint32_t kcol = ks * 16;
            uint32_t ah[2][4];
#pragma unroll
            for (int mt = 0; mt < 2; mt++) {
                uint32_t off = ((a_row + mt * 16) * 72 + kcol + a_kg) * 2;
                ldsm_x4(ah[mt], base + off);
            }
#pragma unroll
            for (int ntp = 0; ntp < 2; ntp++) {
                uint32_t boff = ((b_row4 + ntp * 16) * 72 + kcol + b_kg) * 2;
                uint32_t bb[4];
                ldsm_x4(bb, base + 36864u - 18432u + boff);   // B at +18432
#pragma unroll
                for (int mt = 0; mt < 2; mt++) {
                    mma16816(acc[mt][ntp * 2 + 0], ah[mt], bb);
                    mma16816(acc[mt][ntp * 2 + 1], ah[mt], bb + 2);
                }
            }
            if (MODE == 0 && ks == 1 && nxt) store_A(st ^ 1);
        }

        if (nxt) CP_WAIT0();
        __syncthreads();
    }

    // Epilogue
#pragma unroll
    for (int mt = 0; mt < 2; mt++) {
#pragma unroll
        for (int nt = 0; nt < 4; nt++) {
            const float* c = acc[mt][nt];
            const int col = n0 + wn * 32 + nt * 8 + (lane & 3) * 2;
#pragma unroll
            for (int hr = 0; hr < 2; hr++) {
                const int row = m0 + wm * 32 + mt * 16 + (lane >> 2) + hr * 8;
                float vx = c[hr * 2 + 0], vy = c[hr * 2 + 1];
                if (MODE == 0) {
                    const int part = col >> 10, rr = col & 1023;
                    const int h = rr >> 6, d = rr & 63;
                    const int b = row >> 11, n = row & 2047;
                    const size_t addr = ((size_t)(b * HH + h) * NN + n) * DD + d;
                    if (part == 0) { vx *= QSCALE; vy *= QSCALE; }
                    __half* dst = (part == 0) ? g_qh : (part == 1) ? g_kh : g_vh;
                    *(uint32_t*)&dst[addr] = packf16x2(vx, vy);
                } else {
                    vx += bias[col];
                    vy += bias[col + 1];
                    *(float2*)&outp[(size_t)row * CC + col] = make_float2(vx, vy);
                }
            }
        }
    }
}

// ---------------- MMA flash attention: fp16, deferred-l, skip-rescale --------
// Smem: 2 stages x (Kh|Vh)[64][72] = 36864 B. Qh staging overlays stage 0.
#define ATT_SMEM 36864
__global__ __launch_bounds__(256, 2) void attn_mma_kernel()
{
    extern __shared__ __half smh[];
    const int bh   = blockIdx.y;
    const int q0   = blockIdx.x * 128;
    const int tid  = threadIdx.x;
    const int lane = tid & 31;
    const int warp = tid >> 5;

    const uint32_t sbase = smem_u32(smh);
    const size_t hb = (size_t)bh * NN * DD;
    const __half* kvsrc[2] = { g_kh + hb, g_vh + hb };

    // ---- prologue ----
#pragma unroll
    for (int i = 0; i < 4; i++) {
        const int s = tid + i * 256;
        const int row = s >> 3, c = (s & 7) * 8;
        cp16(sbase + (row * 72 + c) * 2, g_qh + hb + (size_t)(q0 + row) * DD + c);
    }
    CP_COMMIT();
#pragma unroll
    for (int i = 0; i < 4; i++) {
        const int mat = i >> 1;
        const int s = tid + (i & 1) * 256;
        const int row = s >> 3, c = (s & 7) * 8;
        cp16(sbase + 18432 + mat * 9216 + (row * 72 + c) * 2,
             kvsrc[mat] + (size_t)row * DD + c);
    }
    CP_COMMIT();
    CP_WAIT1();
    __syncthreads();

    uint32_t qh[4][4];
    {
        const uint32_t arow = warp * 16 + (lane & 15);
        const uint32_t akg  = ((lane >> 4) & 1) * 8;
#pragma unroll
        for (int ks = 0; ks < 4; ks++)
            ldsm_x4(qh[ks], sbase + (arow * 72 + ks * 16 + akg) * 2);
    }
    __syncthreads();

    float O[8][4];
#pragma unroll
    for (int n = 0; n < 8; n++)
#pragma unroll
        for (int c = 0; c < 4; c++) O[n][c] = 0.0f;
    float m0r = -1e30f, m1r = -1e30f;
    float l0 = 0.0f, l1 = 0.0f;        // per-thread partials; reduced at end

    const uint32_t b_kg   = ((lane >> 3) & 1) * 8;
    const uint32_t b_row4 = (lane & 7) + (((lane >> 4) & 1) << 3);

    for (int t = 0; t < 32; t++) {
        const uint32_t base = sbase + ((t & 1) ? 0u : 18432u);

        if (t + 1 < 32) {
            const uint32_t nbase = sbase + ((t & 1) ? 18432u : 0u);
            const int j0 = (t + 1) * 64;
#pragma unroll
            for (int i = 0; i < 4; i++) {
                const int mat = i >> 1;
                const int s = tid + (i & 1) * 256;
                const int row = s >> 3, c = (s & 7) * 8;
                cp16(nbase + mat * 9216 + (row * 72 + c) * 2,
                     kvsrc[mat] + (size_t)(j0 + row) * DD + c);
            }
            CP_COMMIT();
            CP_WAIT1();
        } else {
            CP_WAIT0();
        }
        __syncthreads();

        // ---- scores ----
        float s[8][4];
#pragma unroll
        for (int n = 0; n < 8; n++)
#pragma unroll
            for (int c = 0; c < 4; c++) s[n][c] = 0.0f;

#pragma unroll
        for (int ks = 0; ks < 4; ks++) {
#pragma unroll
            for (int ntp = 0; ntp < 4; ntp++) {
                uint32_t boff = ((b_row4 + ntp * 16) * 72 + ks * 16 + b_kg) * 2;
                uint32_t kb[4];
                ldsm_x4(kb, base + boff);
                mma16816(s[ntp * 2 + 0], qh[ks], kb);
                mma16816(s[ntp * 2 + 1], qh[ks], kb + 2);
            }
        }

        // ---- online softmax ----
        float mloc0 = -1e30f, mloc1 = -1e30f;
#pragma unroll
        for (int nt = 0; nt < 8; nt++) {
            mloc0 = fmaxf(mloc0, fmaxf(s[nt][0], s[nt][1]));
            mloc1 = fmaxf(mloc1, fmaxf(s[nt][2], s[nt][3]));
        }
        mloc0 = fmaxf(mloc0, __shfl_xor_sync(0xffffffffu, mloc0, 1));
        mloc0 = fmaxf(mloc0, __shfl_xor_sync(0xffffffffu, mloc0, 2));
        mloc1 = fmaxf(mloc1, __shfl_xor_sync(0xffffffffu, mloc1, 1));
        mloc1 = fmaxf(mloc1, __shfl_xor_sync(0xffffffffu, mloc1, 2));

        const float mn0 = fmaxf(m0r, mloc0), mn1 = fmaxf(m1r, mloc1);
        if (__any_sync(0xffffffffu, (mn0 > m0r) || (mn1 > m1r))) {
            const float cr0 = ex2f(m0r - mn0), cr1 = ex2f(m1r - mn1);
            m0r = mn0; m1r = mn1;
            l0 *= cr0; l1 *= cr1;
#pragma unroll
            for (int n = 0; n < 8; n++) {
                O[n][0] *= cr0; O[n][1] *= cr0;
                O[n][2] *= cr1; O[n][3] *= cr1;
            }
        }

        uint32_t aPh[4][4];
#pragma unroll
        for (int nt = 0; nt < 8; nt++) {
            float p0 = ex2f(s[nt][0] - m0r);
            float p1 = ex2f(s[nt][1] - m0r);
            float p2 = ex2f(s[nt][2] - m1r);
            float p3 = ex2f(s[nt][3] - m1r);
            l0 += p0 + p1; l1 += p2 + p3;
            const int kt = nt >> 1, hi2 = (nt & 1) * 2;
            aPh[kt][hi2 + 0] = packf16x2(p0, p1);
            aPh[kt][hi2 + 1] = packf16x2(p2, p3);
        }

        // ---- O += PhVh ----
#pragma unroll
        for (int ktp = 0; ktp < 2; ktp++) {
#pragma unroll
            for (int nd = 0; nd < 8; nd++) {
                uint32_t voff = ((ktp * 32 + lane) * 72 + nd * 8) * 2;
                uint32_t vb[4];
                ldsm_x4t(vb, base + 9216 + voff);
                mma16816(O[nd], aPh[ktp * 2 + 0], vb);
                mma16816(O[nd], aPh[ktp * 2 + 1], vb + 2);
            }
        }
        __syncthreads();
    }

    // ---- final l reduction (quad) + epilogue ----
    l0 += __shfl_xor_sync(0xffffffffu, l0, 1);
    l0 += __shfl_xor_sync(0xffffffffu, l0, 2);
    l1 += __shfl_xor_sync(0xffffffffu, l1, 1);
    l1 += __shfl_xor_sync(0xffffffffu, l1, 2);
    const float inv0 = 1.0f / l0, inv1 = 1.0f / l1;
    const int b = bh >> 4, h = bh & 15;
    const int row0 = q0 + warp * 16 + (lane >> 2);
    const int row1 = row0 + 8;
#pragma unroll
    for (int nd = 0; nd < 8; nd++) {
        const int d = nd * 8 + (lane & 3) * 2;
        const size_t a0 = ((size_t)(b * NN + row0)) * CC + h * DD + d;
        const size_t a1 = ((size_t)(b * NN + row1)) * CC + h * DD + d;
        *(uint32_t*)&g_aoh[a0] = packf16x2(O[nd][0] * inv0, O[nd][1] * inv0);
        *(uint32_t*)&g_aoh[a1] = packf16x2(O[nd][2] * inv1, O[nd][3] * inv1);
    }
}

// ---------------------------------------------------------------------------
extern "C" void kernel_launch(void* const* d_in, const int* in_sizes, int n_in,
                              void* d_out, int out_size)
{
    const float* x     = (const float*)d_in[0];
    const float* W_qkv = (const float*)d_in[1];
    const float* W_out = (const float*)d_in[2];
    const float* b_out = (const float*)d_in[3];
    float* out = (float*)d_out;
    (void)in_sizes; (void)n_in; (void)out_size;

    cudaFuncSetAttribute(tc_gemm<0>, cudaFuncAttributeMaxDynamicSharedMemorySize, GSMEM);
    cudaFuncSetAttribute(tc_gemm<1>, cudaFuncAttributeMaxDynamicSharedMemorySize, GSMEM);
    cudaFuncSetAttribute(attn_mma_kernel, cudaFuncAttributeMaxDynamicSharedMemorySize, ATT_SMEM);

    whalf_kernel<<<(NQ4 + NO4 + 255) / 256, 256>>>(W_qkv, W_out);

    {
        dim3 grid(E3 / 128, MM / 128);   // (24, 32)
        tc_gemm<0><<<grid, 512, GSMEM>>>(x, nullptr, nullptr);
    }
    {
        dim3 grid(NN / 128, BH);         // (16, 32)
        attn_mma_kernel<<<grid, 256, ATT_SMEM>>>();
    }
    {
        dim3 grid(CC / 128, MM / 128);   // (8, 32)
        tc_gemm<1><<<grid, 512, GSMEM>>>(nullptr, b_out, out);
    }
}